// round 16
// baseline (speedup 1.0000x reference)
#include <cuda_runtime.h>
#include <cuda_bf16.h>
#include <cuda_fp16.h>
#include <cstdint>

#define Bn 64
#define Sn 1024
#define Xn 256
#define Yn 128

typedef unsigned int uint;
typedef unsigned short ushort;

// ---------------- scratch (device globals: no cudaMalloc allowed) ----------
__device__ ushort        g_qf[Bn * Sn * Xn];   // q fp16
__device__ ushort        g_Wf[3][Yn * Xn];     // Wq/Wk/Wv fp16
__device__ ushort        g_Qf[Bn * Sn * Yn];   // Q fp16
__device__ ushort        g_Kf[Bn * Sn * Yn];   // K fp16
__device__ ushort        g_Vf[Bn * Sn * Yn];   // V fp16 (pre-norm) [b][k][d]
__device__ ushort        g_P [(size_t)Bn * Sn * Sn];  // exp(S) fp16, 128MB
__device__ float         g_pz[Bn * 8 * Sn];    // per-(b,qt,k) tile col sum-exp

// ---------------- shared tile layouts ------------------------------------------
// A-tiles (m x k): 128 rows x 64 halves, stride 72 (144B: rows at 16r mod 128).
#define TS2   72
#define PVT(i) ((i) * 128 * TS2)            // half offset of sub-tile i (18432B)
#define SM_1P   (6 * 128 * TS2 * 2)         // 110592 B (qkv/scores: 2 tiles x 3 stages)

// pv B-tiles ([k][d]): 64 rows x 128 halves, stride 136 (272B: rows at 16r mod 128).
#define TSB   136
#define PV_A(s) ((s) * 18432)               // byte offset, A stage s
#define PV_B(s) (3 * 18432 + (s) * 17408)   // byte offset, B stage s
#define PV_ZR   (3 * 18432 + 3 * 17408)     // byte offset, zr half2 array [1024]
#define SM_PV   (PV_ZR + 4096)              // 111616 B

// ---------------- helpers ------------------------------------------------------
__device__ __forceinline__ ushort f2h(float v) {
    return __half_as_ushort(__float2half_rn(v));
}

__device__ __forceinline__ uint32_t smem_u32(const void* p) {
    uint32_t a;
    asm("{ .reg .u64 t; cvta.to.shared.u64 t, %1; cvt.u32.u64 %0, t; }" : "=r"(a) : "l"(p));
    return a;
}

__device__ __forceinline__ void mma_f16(float* c, const uint* a, const uint* b) {
    asm volatile("mma.sync.aligned.m16n8k16.row.col.f32.f16.f16.f32 "
        "{%0,%1,%2,%3}, {%4,%5,%6,%7}, {%8,%9}, {%0,%1,%2,%3};"
        : "+f"(c[0]), "+f"(c[1]), "+f"(c[2]), "+f"(c[3])
        : "r"(a[0]), "r"(a[1]), "r"(a[2]), "r"(a[3]), "r"(b[0]), "r"(b[1]));
}

#define LDSM4(r0, r1, r2, r3, addr) \
    asm volatile("ldmatrix.sync.aligned.m8n8.x4.shared.b16 {%0,%1,%2,%3}, [%4];" \
        : "=r"(r0), "=r"(r1), "=r"(r2), "=r"(r3) : "r"(addr))
#define LDSM4T(r0, r1, r2, r3, addr) \
    asm volatile("ldmatrix.sync.aligned.m8n8.x4.trans.shared.b16 {%0,%1,%2,%3}, [%4];" \
        : "=r"(r0), "=r"(r1), "=r"(r2), "=r"(r3) : "r"(addr))

#define CP_ASYNC16(dst, src) \
    asm volatile("cp.async.cg.shared.global [%0], [%1], 16;" :: "r"(dst), "l"(src))
#define CP_COMMIT() asm volatile("cp.async.commit_group;" ::: "memory")
#define CP_WAIT(N)  asm volatile("cp.async.wait_group %0;" :: "n"(N) : "memory")

__device__ __forceinline__ void atomicMaxF(float* a, float v) {
    if (v >= 0.f) atomicMax((int*)a, __float_as_int(v));
    else          atomicMin((uint*)a, (uint)__float_as_int(v));
}

// Async tile fill: 128 rows x 64 halves, stride TS2.
__device__ __forceinline__ void fill_tile64_async(uint32_t dst, const ushort* src,
                                                  int stride, int tid) {
    #pragma unroll
    for (int it = 0; it < 4; it++) {
        int idx  = it * 256 + tid;
        int row  = idx >> 3;
        int col8 = (idx & 7) << 3;
        CP_ASYNC16(dst + (uint32_t)(row * TS2 + col8) * 2,
                   src + (size_t)row * stride + col8);
    }
}

// Async B tile fill for pv: 64 rows x 128 halves, stride TSB; src stride Yn=128.
__device__ __forceinline__ void fill_tileB_async(uint32_t dst, const ushort* src,
                                                 int tid) {
    #pragma unroll
    for (int it = 0; it < 4; it++) {
        int idx  = it * 256 + tid;
        int row  = idx >> 4;
        int col8 = (idx & 15) << 3;
        CP_ASYNC16(dst + (uint32_t)(row * TSB + col8) * 2,
                   src + (size_t)row * Yn + col8);
    }
}

__device__ __forceinline__ uint32_t a_lane_off(int m0, int lane) {
    int r = lane & 7, grp = lane >> 3;
    return (uint32_t)(((m0 + (grp & 1) * 8 + r) * TS2 + (grp >> 1) * 8) * 2);
}
__device__ __forceinline__ uint32_t b_lane_off(int n0, int lane) {
    int r = lane & 7, grp = lane >> 3;
    return (uint32_t)(((n0 + (grp >> 1) * 8 + r) * TS2 + (grp & 1) * 8) * 2);
}
// trans B lane offset ([k][d] tile): row k = lane&15, col half-group = 8*(lane>>4)
__device__ __forceinline__ uint32_t bT_lane_off(int n0, int lane) {
    return (uint32_t)(((lane & 15) * TSB + n0 + ((lane >> 4) << 3)) * 2);
}

// ---- single-pass fp16 chunk (k=64), A[m][k] + B[n][k], strides TS2 ------------
__device__ __forceinline__ void warp_mma64_1p(float (&c)[2][8][4],
        uint32_t aP, uint32_t bP) {
    #pragma unroll
    for (int ks = 0; ks < 4; ks++) {
        const uint32_t ko = ks * 32;
        uint a[2][4], b[4][4];
        #pragma unroll
        for (int tm = 0; tm < 2; tm++)
            LDSM4(a[tm][0], a[tm][1], a[tm][2], a[tm][3], aP + tm * (16 * TS2 * 2) + ko);
        #pragma unroll
        for (int p = 0; p < 4; p++)
            LDSM4(b[p][0], b[p][1], b[p][2], b[p][3], bP + p * (16 * TS2 * 2) + ko);
        #pragma unroll
        for (int tm = 0; tm < 2; tm++) {
            #pragma unroll
            for (int tn = 0; tn < 8; tn++) {
                const int p = tn >> 1, s = (tn & 1) * 2;
                mma_f16(c[tm][tn], a[tm], &b[p][s]);
            }
        }
    }
}

// ---- pv chunk: A[m][k] stride TS2 + B[k][d] stride TSB via ldmatrix.trans -----
__device__ __forceinline__ void warp_mma64_trans(float (&c)[2][8][4],
        uint32_t aP, uint32_t bP) {
    #pragma unroll
    for (int ks = 0; ks < 4; ks++) {
        uint a[2][4], b[4][4];
        #pragma unroll
        for (int tm = 0; tm < 2; tm++)
            LDSM4(a[tm][0], a[tm][1], a[tm][2], a[tm][3],
                  aP + tm * (16 * TS2 * 2) + ks * 32);
        #pragma unroll
        for (int p = 0; p < 4; p++)
            LDSM4T(b[p][0], b[p][1], b[p][2], b[p][3],
                   bP + ks * (16 * TSB * 2) + p * 32);
        #pragma unroll
        for (int tm = 0; tm < 2; tm++) {
            #pragma unroll
            for (int tn = 0; tn < 8; tn++) {
                const int p = tn >> 1, s = (tn & 1) * 2;
                mma_f16(c[tm][tn], a[tm], &b[p][s]);
            }
        }
    }
}

// ---- 3-stage pipeline (qkv/scores), single sync per iteration -------------------
template <int NCH>
__device__ __forceinline__ void pipe1_mma(float (&c)[2][8][4], uint32_t base,
        uint32_t aoff, uint32_t boff,
        const ushort* a, int sa, const ushort* b, int sb, int tid) {
    fill_tile64_async(base + PVT(0) * 2, a, sa, tid);
    fill_tile64_async(base + PVT(1) * 2, b, sb, tid);
    CP_COMMIT();
    if (NCH > 1) {
        fill_tile64_async(base + PVT(2) * 2, a + 64, sa, tid);
        fill_tile64_async(base + PVT(3) * 2, b + 64, sb, tid);
        CP_COMMIT();
    }
    #pragma unroll
    for (int ch = 0; ch < NCH; ch++) {
        const int st = ch % 3;
        if (ch < NCH - 1) { CP_WAIT(1); } else { CP_WAIT(0); }
        __syncthreads();
        if (ch + 2 < NCH) {
            const int sn = (ch + 2) % 3;
            const int kn = (ch + 2) * 64;
            fill_tile64_async(base + PVT(2 * sn) * 2,     a + kn, sa, tid);
            fill_tile64_async(base + PVT(2 * sn + 1) * 2, b + kn, sb, tid);
            CP_COMMIT();
        }
        warp_mma64_1p(c, base + PVT(2 * st) * 2 + aoff,
                         base + PVT(2 * st + 1) * 2 + boff);
    }
}

// ---------------- K0: fused prep: q->fp16, W->fp16, out->-inf ------------------
__global__ void prep_kernel(const float* __restrict__ q,
                            const float* __restrict__ Wq,
                            const float* __restrict__ Wk,
                            const float* __restrict__ Wv,
                            float* __restrict__ out) {
    const int bid = blockIdx.x;
    const int tid = threadIdx.x;
    if (bid < 16384) {
        int i = (bid * 256 + tid) * 4;
        float4 v = *(const float4*)(q + i);
        uint2 u;
        u.x = (uint)f2h(v.x) | ((uint)f2h(v.y) << 16);
        u.y = (uint)f2h(v.z) | ((uint)f2h(v.w) << 16);
        *(uint2*)(g_qf + i) = u;
    } else if (bid < 16480) {
        const int bid2 = bid - 16384;
        const int sel = bid2 >> 5;
        const int blk = bid2 & 31;
        const float* src = (sel == 0) ? Wq : (sel == 1) ? Wk : Wv;
        int i = (blk * 256 + tid) * 4;
        float4 v = *(const float4*)(src + i);
        uint2 u;
        u.x = (uint)f2h(v.x) | ((uint)f2h(v.y) << 16);
        u.y = (uint)f2h(v.z) | ((uint)f2h(v.w) << 16);
        *(uint2*)(g_Wf[sel] + i) = u;
    } else {
        int i = (bid - 16480) * 256 + tid;
        out[i] = __int_as_float(0xFF800000);
    }
}

// ---------------- K1: QKV projection (fp16 single-pass, 4 chunks) --------------
__global__ __launch_bounds__(256, 2)
void qkv_mma_kernel(const float* __restrict__ bq, const float* __restrict__ bk,
                    const float* __restrict__ bv) {
    extern __shared__ ushort sh[];
    const int tid = threadIdx.x;
    const int w = tid >> 5, lane = tid & 31, g = lane >> 2, t = lane & 3;
    const int m0 = (w & 3) * 32, n0 = (w >> 2) * 64;
    const int rowBase = blockIdx.x * 128;
    const int sel = blockIdx.y;

    const uint32_t base = smem_u32(sh);
    const uint32_t aoff = a_lane_off(m0, lane), boff = b_lane_off(n0, lane);

    float c[2][8][4];
    #pragma unroll
    for (int i = 0; i < 2; i++)
        #pragma unroll
        for (int j = 0; j < 8; j++)
            #pragma unroll
            for (int r = 0; r < 4; r++) c[i][j][r] = 0.f;

    pipe1_mma<4>(c, base, aoff, boff,
                 g_qf + (size_t)rowBase * Xn, Xn, g_Wf[sel], Xn, tid);

    const float* bias = (sel == 0) ? bq : (sel == 1) ? bk : bv;
    ushort* dst = (sel == 0) ? g_Qf : (sel == 1) ? g_Kf : g_Vf;
    #pragma unroll
    for (int tm = 0; tm < 2; tm++) {
        #pragma unroll
        for (int half = 0; half < 2; half++) {
            const int mloc = m0 + tm * 16 + g + half * 8;
            const size_t row = (size_t)(rowBase + mloc) * Yn;
            #pragma unroll
            for (int tn = 0; tn < 8; tn++) {
                const int n = n0 + tn * 8 + t * 2;
                float v0 = c[tm][tn][half * 2 + 0] + __ldg(bias + n);
                float v1 = c[tm][tn][half * 2 + 1] + __ldg(bias + n + 1);
                *(uint*)(dst + row + n) = (uint)f2h(v0) | ((uint)f2h(v1) << 16);
            }
        }
    }
}

// ---------------- K2: scores (fp16 single-pass) -> P fp16 + sums ---------------
__global__ __launch_bounds__(256, 2)
void scores_mma_kernel() {
    extern __shared__ ushort sh[];
    const int tid = threadIdx.x;
    const int w = tid >> 5, lane = tid & 31, g = lane >> 2, t = lane & 3;
    const int m0 = (w & 3) * 32, n0 = (w >> 2) * 64, mw = w & 3;
    const int kt = blockIdx.x, qt = blockIdx.y, b = blockIdx.z;

    const uint32_t base = smem_u32(sh);
    const uint32_t aoff = a_lane_off(m0, lane), boff = b_lane_off(n0, lane);

    float c[2][8][4];
    #pragma unroll
    for (int i = 0; i < 2; i++)
        #pragma unroll
        for (int j = 0; j < 8; j++)
            #pragma unroll
            for (int r = 0; r < 4; r++) c[i][j][r] = 0.f;

    const size_t qoff = ((size_t)b * Sn + qt * 128) * Yn;
    const size_t koff = ((size_t)b * Sn + kt * 128) * Yn;
    pipe1_mma<2>(c, base, aoff, boff, g_Qf + qoff, Yn, g_Kf + koff, Yn, tid);

    // c := exp(c * scale) in place
    const float scale = 0.08838834764831845f;  // 1/sqrt(128)
    #pragma unroll
    for (int i = 0; i < 2; i++)
        #pragma unroll
        for (int j = 0; j < 8; j++)
            #pragma unroll
            for (int r = 0; r < 4; r++) c[i][j][r] = __expf(c[i][j][r] * scale);

    // write P (fp16)
    ushort* Pp = g_P + (size_t)b * Sn * Sn;
    #pragma unroll
    for (int tm = 0; tm < 2; tm++) {
        #pragma unroll
        for (int half = 0; half < 2; half++) {
            const size_t m = (size_t)(qt * 128 + m0 + tm * 16 + g + half * 8);
            #pragma unroll
            for (int tn = 0; tn < 8; tn++) {
                const int n = kt * 128 + n0 + tn * 8 + t * 2;
                *(uint*)(Pp + m * Sn + n) =
                    (uint)f2h(c[tm][tn][half * 2 + 0]) |
                    ((uint)f2h(c[tm][tn][half * 2 + 1]) << 16);
            }
        }
    }

    // per-tile column sums of exp over this CTA's 128 q rows
    __syncthreads();                       // tiles no longer needed; reuse smem
    float* szz = (float*)sh;               // [128][4]
    float vz[16];
    #pragma unroll
    for (int tn = 0; tn < 8; tn++) {
        #pragma unroll
        for (int par = 0; par < 2; par++) {
            float z = c[0][tn][par] + c[0][tn][2 + par]
                    + c[1][tn][par] + c[1][tn][2 + par];
            z += __shfl_xor_sync(0xFFFFFFFF, z, 4);
            z += __shfl_xor_sync(0xFFFFFFFF, z, 8);
            z += __shfl_xor_sync(0xFFFFFFFF, z, 16);
            vz[tn * 2 + par] = z;
        }
    }
    if (lane < 4) {
        #pragma unroll
        for (int tn = 0; tn < 8; tn++)
            #pragma unroll
            for (int par = 0; par < 2; par++)
                szz[(n0 + tn * 8 + t * 2 + par) * 4 + mw] = vz[tn * 2 + par];
    }
    __syncthreads();
    if (tid < 128) {
        const int n = tid;
        const float z = szz[n * 4 + 0] + szz[n * 4 + 1] + szz[n * 4 + 2] + szz[n * 4 + 3];
        g_pz[((size_t)(b * 8 + qt)) * Sn + kt * 128 + n] = z;
    }
}

// ---------------- K3: PV (fp16, B via ldmatrix.trans, 1/Z fused) + max ---------
__global__ __launch_bounds__(256, 2)
void pv_mma_kernel(float* __restrict__ out) {
    extern __shared__ ushort sh[];
    const int tid = threadIdx.x;
    const int w = tid >> 5, lane = tid & 31, t = lane & 3;
    const int m0 = (w & 3) * 32, n0 = (w >> 2) * 64;
    const int qt = blockIdx.x, b = blockIdx.y;

    const uint32_t base = smem_u32(sh);
    const uint32_t aoff = a_lane_off(m0, lane), boff = bT_lane_off(n0, lane);

    const ushort* Pp = g_P + (size_t)b * Sn * Sn + (size_t)(qt * 128) * Sn;
    const ushort* Vp = g_Vf + (size_t)b * Sn * Yn;   // raw V [k][d]
    uint* zr2 = (uint*)((char*)sh + PV_ZR);          // half2(1/Z) per k, [1024]

    float c[2][8][4];
    #pragma unroll
    for (int i = 0; i < 2; i++)
        #pragma unroll
        for (int j = 0; j < 8; j++)
            #pragma unroll
            for (int r = 0; r < 4; r++) c[i][j][r] = 0.f;

    // precompute 1/Z for all 1024 k (each thread: 4 k values)
    #pragma unroll
    for (int j = 0; j < 4; j++) {
        const int k = tid * 4 + j;
        float z = 0.f;
        #pragma unroll
        for (int i = 0; i < 8; i++)
            z += g_pz[((size_t)(b * 8 + i)) * Sn + k];
        const ushort h = f2h(1.0f / z);
        zr2[k] = (uint)h | ((uint)h << 16);
    }

    // 3-stage pipeline; B tiles scaled by 1/Z[k] in smem after arrival
    fill_tile64_async(base + PV_A(0), Pp, Sn, tid);
    fill_tileB_async (base + PV_B(0), Vp, tid);
    CP_COMMIT();
    fill_tile64_async(base + PV_A(1), Pp + 64, Sn, tid);
    fill_tileB_async (base + PV_B(1), Vp + 64 * Yn, tid);
    CP_COMMIT();
    #pragma unroll
    for (int ch = 0; ch < 16; ch++) {
        const int st = ch % 3;
        if (ch < 15) { CP_WAIT(1); } else { CP_WAIT(0); }
        __syncthreads();
        if (ch + 2 < 16) {
            const int sn = (ch + 2) % 3;
            fill_tile64_async(base + PV_A(sn), Pp + (ch + 2) * 64, Sn, tid);
            fill_tileB_async (base + PV_B(sn), Vp + (size_t)(ch + 2) * 64 * Yn, tid);
            CP_COMMIT();
        }
        // scale current B tile rows by half2(1/Z[k]) in place
        {
            const int k0 = ch * 64;
            #pragma unroll
            for (int it = 0; it < 4; it++) {
                const int idx  = it * 256 + tid;
                const int row  = idx >> 4;
                const int col8 = (idx & 15) << 3;
                uint4* p = (uint4*)((char*)sh + PV_B(st) + (size_t)(row * TSB + col8) * 2);
                uint4 u = *p;
                const uint z2 = zr2[k0 + row];
                uint r0, r1, r2, r3;
                asm("mul.rn.f16x2 %0, %1, %2;" : "=r"(r0) : "r"(u.x), "r"(z2));
                asm("mul.rn.f16x2 %0, %1, %2;" : "=r"(r1) : "r"(u.y), "r"(z2));
                asm("mul.rn.f16x2 %0, %1, %2;" : "=r"(r2) : "r"(u.z), "r"(z2));
                asm("mul.rn.f16x2 %0, %1, %2;" : "=r"(r3) : "r"(u.w), "r"(z2));
                *p = make_uint4(r0, r1, r2, r3);
            }
        }
        __syncthreads();
        warp_mma64_trans(c, base + PV_A(st) + aoff, base + PV_B(st) + boff);
    }

    // fused max over q: thread-local max, shuffle-reduce over g, one atomic per n.
    #pragma unroll
    for (int tn = 0; tn < 8; tn++) {
        #pragma unroll
        for (int par = 0; par < 2; par++) {
            float v = c[0][tn][par];
            v = fmaxf(v, c[0][tn][2 + par]);
            v = fmaxf(v, c[1][tn][par]);
            v = fmaxf(v, c[1][tn][2 + par]);
            v = fmaxf(v, __shfl_xor_sync(0xFFFFFFFF, v, 4));
            v = fmaxf(v, __shfl_xor_sync(0xFFFFFFFF, v, 8));
            v = fmaxf(v, __shfl_xor_sync(0xFFFFFFFF, v, 16));
            if (lane < 4)
                atomicMaxF(out + b * Yn + n0 + tn * 8 + t * 2 + par, v);
        }
    }
}

// ============================================================================
extern "C" void kernel_launch(void* const* d_in, const int* in_sizes, int n_in,
                              void* d_out, int out_size)
{
    const float* q  = (const float*)d_in[0];
    const float* Wq = (const float*)d_in[1];
    const float* bq = (const float*)d_in[2];
    const float* Wk = (const float*)d_in[3];
    const float* bk = (const float*)d_in[4];
    const float* Wv = (const float*)d_in[5];
    const float* bv = (const float*)d_in[6];
    float* out = (float*)d_out;

    cudaFuncSetAttribute(qkv_mma_kernel,    cudaFuncAttributeMaxDynamicSharedMemorySize, SM_1P);
    cudaFuncSetAttribute(scores_mma_kernel, cudaFuncAttributeMaxDynamicSharedMemorySize, SM_1P);
    cudaFuncSetAttribute(pv_mma_kernel,     cudaFuncAttributeMaxDynamicSharedMemorySize, SM_PV);

    prep_kernel<<<16512, 256>>>(q, Wq, Wk, Wv, out);
    qkv_mma_kernel<<<dim3(Bn * Sn / 128, 3), 256, SM_1P>>>(bq, bk, bv);
    scores_mma_kernel<<<dim3(Sn / 128, Sn / 128, Bn), 256, SM_1P>>>();
    pv_mma_kernel<<<dim3(Sn / 128, Bn), 256, SM_PV>>>(out);
}

// round 17
// speedup vs baseline: 1.0180x; 1.0180x over previous
#include <cuda_runtime.h>
#include <cuda_bf16.h>
#include <cuda_fp16.h>
#include <cstdint>

#define Bn 64
#define Sn 1024
#define Xn 256
#define Yn 128

typedef unsigned int uint;
typedef unsigned short ushort;

// ---------------- scratch (device globals: no cudaMalloc allowed) ----------
__device__ ushort        g_qf[Bn * Sn * Xn];   // q fp16
__device__ ushort        g_Wf[3][Yn * Xn];     // Wq/Wk/Wv fp16
__device__ ushort        g_Qf[Bn * Sn * Yn];   // Q fp16
__device__ ushort        g_Kf[Bn * Sn * Yn];   // K fp16
__device__ ushort        g_Vf[Bn * Sn * Yn];   // V fp16 (pre-norm) [b][k][d]
__device__ ushort        g_P [(size_t)Bn * Sn * Sn];  // exp(S) fp16, 128MB
__device__ float         g_pz[Bn * 8 * Sn];    // per-(b,qt,k) tile col sum-exp
__device__ ushort        g_Vt[Bn * Sn * Yn];   // V/Z fp16 [b][k][d]

// ---------------- shared tile layouts ------------------------------------------
// qkv/scores A/B tiles (x x 64k): 128 rows x 64 halves, stride 72.
#define TS2   72
#define PVT(i) ((i) * 128 * TS2)            // half offset of sub-tile i (18432B)
#define SM_1P   (6 * 128 * TS2 * 2)         // 110592 B (2 tiles x 3 stages)

// pv: A tiles 64q x 64k (stride 72, 9216B); B tiles 64k x 128d (stride 136, 17408B)
#define TSB   136
#define PA(s) ((s) * 9216)                  // byte offset, A stage s (4 stages)
#define PB(s) (4 * 9216 + (s) * 17408)      // byte offset, B stage s
#define SM_PV (4 * 9216 + 4 * 17408)        // 106496 B

// ---------------- helpers ------------------------------------------------------
__device__ __forceinline__ ushort f2h(float v) {
    return __half_as_ushort(__float2half_rn(v));
}
__device__ __forceinline__ float h2f(ushort v) {
    return __half2float(__ushort_as_half(v));
}

__device__ __forceinline__ uint32_t smem_u32(const void* p) {
    uint32_t a;
    asm("{ .reg .u64 t; cvta.to.shared.u64 t, %1; cvt.u32.u64 %0, t; }" : "=r"(a) : "l"(p));
    return a;
}

__device__ __forceinline__ void mma_f16(float* c, const uint* a, const uint* b) {
    asm volatile("mma.sync.aligned.m16n8k16.row.col.f32.f16.f16.f32 "
        "{%0,%1,%2,%3}, {%4,%5,%6,%7}, {%8,%9}, {%0,%1,%2,%3};"
        : "+f"(c[0]), "+f"(c[1]), "+f"(c[2]), "+f"(c[3])
        : "r"(a[0]), "r"(a[1]), "r"(a[2]), "r"(a[3]), "r"(b[0]), "r"(b[1]));
}

#define LDSM4(r0, r1, r2, r3, addr) \
    asm volatile("ldmatrix.sync.aligned.m8n8.x4.shared.b16 {%0,%1,%2,%3}, [%4];" \
        : "=r"(r0), "=r"(r1), "=r"(r2), "=r"(r3) : "r"(addr))
#define LDSM4T(r0, r1, r2, r3, addr) \
    asm volatile("ldmatrix.sync.aligned.m8n8.x4.trans.shared.b16 {%0,%1,%2,%3}, [%4];" \
        : "=r"(r0), "=r"(r1), "=r"(r2), "=r"(r3) : "r"(addr))

#define CP_ASYNC16(dst, src) \
    asm volatile("cp.async.cg.shared.global [%0], [%1], 16;" :: "r"(dst), "l"(src))
#define CP_COMMIT() asm volatile("cp.async.commit_group;" ::: "memory")
#define CP_WAIT(N)  asm volatile("cp.async.wait_group %0;" :: "n"(N) : "memory")

__device__ __forceinline__ void atomicMaxF(float* a, float v) {
    if (v >= 0.f) atomicMax((int*)a, __float_as_int(v));
    else          atomicMin((uint*)a, (uint)__float_as_int(v));
}

// Async tile fill: 128 rows x 64 halves, stride TS2.
__device__ __forceinline__ void fill_tile64_async(uint32_t dst, const ushort* src,
                                                  int stride, int tid) {
    #pragma unroll
    for (int it = 0; it < 4; it++) {
        int idx  = it * 256 + tid;
        int row  = idx >> 3;
        int col8 = (idx & 7) << 3;
        CP_ASYNC16(dst + (uint32_t)(row * TS2 + col8) * 2,
                   src + (size_t)row * stride + col8);
    }
}

// Async A tile fill for pv: 64 rows x 64 halves, stride TS2.
__device__ __forceinline__ void fill_tileA64_async(uint32_t dst, const ushort* src,
                                                   int stride, int tid) {
    #pragma unroll
    for (int it = 0; it < 2; it++) {
        int idx  = it * 256 + tid;
        int row  = idx >> 3;
        int col8 = (idx & 7) << 3;
        CP_ASYNC16(dst + (uint32_t)(row * TS2 + col8) * 2,
                   src + (size_t)row * stride + col8);
    }
}

// Async B tile fill for pv: 64 rows x 128 halves, stride TSB; src stride Yn=128.
__device__ __forceinline__ void fill_tileB_async(uint32_t dst, const ushort* src,
                                                 int tid) {
    #pragma unroll
    for (int it = 0; it < 4; it++) {
        int idx  = it * 256 + tid;
        int row  = idx >> 4;
        int col8 = (idx & 15) << 3;
        CP_ASYNC16(dst + (uint32_t)(row * TSB + col8) * 2,
                   src + (size_t)row * Yn + col8);
    }
}

__device__ __forceinline__ uint32_t a_lane_off(int m0, int lane) {
    int r = lane & 7, grp = lane >> 3;
    return (uint32_t)(((m0 + (grp & 1) * 8 + r) * TS2 + (grp >> 1) * 8) * 2);
}
__device__ __forceinline__ uint32_t b_lane_off(int n0, int lane) {
    int r = lane & 7, grp = lane >> 3;
    return (uint32_t)(((n0 + (grp >> 1) * 8 + r) * TS2 + (grp & 1) * 8) * 2);
}
// trans B lane offset ([k][d] tile): row k = lane&15, col half-group = 8*(lane>>4)
__device__ __forceinline__ uint32_t bT_lane_off(int n0, int lane) {
    return (uint32_t)(((lane & 15) * TSB + n0 + ((lane >> 4) << 3)) * 2);
}

// ---- single-pass fp16 chunk (k=64), A[m][k] + B[n][k], strides TS2 ------------
__device__ __forceinline__ void warp_mma64_1p(float (&c)[2][8][4],
        uint32_t aP, uint32_t bP) {
    #pragma unroll
    for (int ks = 0; ks < 4; ks++) {
        const uint32_t ko = ks * 32;
        uint a[2][4], b[4][4];
        #pragma unroll
        for (int tm = 0; tm < 2; tm++)
            LDSM4(a[tm][0], a[tm][1], a[tm][2], a[tm][3], aP + tm * (16 * TS2 * 2) + ko);
        #pragma unroll
        for (int p = 0; p < 4; p++)
            LDSM4(b[p][0], b[p][1], b[p][2], b[p][3], bP + p * (16 * TS2 * 2) + ko);
        #pragma unroll
        for (int tm = 0; tm < 2; tm++) {
            #pragma unroll
            for (int tn = 0; tn < 8; tn++) {
                const int p = tn >> 1, s = (tn & 1) * 2;
                mma_f16(c[tm][tn], a[tm], &b[p][s]);
            }
        }
    }
}

// ---- pv chunk: 32m x 32n warp tile; A[m][k] stride TS2, B[k][d] via trans -----
__device__ __forceinline__ void warp_mma32_trans(float (&c)[2][4][4],
        uint32_t aP, uint32_t bP) {
    #pragma unroll
    for (int ks = 0; ks < 4; ks++) {
        uint a[2][4], b[2][4];
        #pragma unroll
        for (int tm = 0; tm < 2; tm++)
            LDSM4(a[tm][0], a[tm][1], a[tm][2], a[tm][3],
                  aP + tm * (16 * TS2 * 2) + ks * 32);
        #pragma unroll
        for (int p = 0; p < 2; p++)
            LDSM4T(b[p][0], b[p][1], b[p][2], b[p][3],
                   bP + ks * (16 * TSB * 2) + p * 32);
        #pragma unroll
        for (int tm = 0; tm < 2; tm++) {
            #pragma unroll
            for (int tn = 0; tn < 4; tn++) {
                const int p = tn >> 1, s = (tn & 1) * 2;
                mma_f16(c[tm][tn], a[tm], &b[p][s]);
            }
        }
    }
}

// ---- 3-stage pipeline (qkv/scores), single sync per iteration -------------------
template <int NCH>
__device__ __forceinline__ void pipe1_mma(float (&c)[2][8][4], uint32_t base,
        uint32_t aoff, uint32_t boff,
        const ushort* a, int sa, const ushort* b, int sb, int tid) {
    fill_tile64_async(base + PVT(0) * 2, a, sa, tid);
    fill_tile64_async(base + PVT(1) * 2, b, sb, tid);
    CP_COMMIT();
    if (NCH > 1) {
        fill_tile64_async(base + PVT(2) * 2, a + 64, sa, tid);
        fill_tile64_async(base + PVT(3) * 2, b + 64, sb, tid);
        CP_COMMIT();
    }
    #pragma unroll
    for (int ch = 0; ch < NCH; ch++) {
        const int st = ch % 3;
        if (ch < NCH - 1) { CP_WAIT(1); } else { CP_WAIT(0); }
        __syncthreads();
        if (ch + 2 < NCH) {
            const int sn = (ch + 2) % 3;
            const int kn = (ch + 2) * 64;
            fill_tile64_async(base + PVT(2 * sn) * 2,     a + kn, sa, tid);
            fill_tile64_async(base + PVT(2 * sn + 1) * 2, b + kn, sb, tid);
            CP_COMMIT();
        }
        warp_mma64_1p(c, base + PVT(2 * st) * 2 + aoff,
                         base + PVT(2 * st + 1) * 2 + boff);
    }
}

// ---------------- K0: fused prep: q->fp16, W->fp16, out->-inf ------------------
__global__ void prep_kernel(const float* __restrict__ q,
                            const float* __restrict__ Wq,
                            const float* __restrict__ Wk,
                            const float* __restrict__ Wv,
                            float* __restrict__ out) {
    const int bid = blockIdx.x;
    const int tid = threadIdx.x;
    if (bid < 16384) {
        int i = (bid * 256 + tid) * 4;
        float4 v = *(const float4*)(q + i);
        uint2 u;
        u.x = (uint)f2h(v.x) | ((uint)f2h(v.y) << 16);
        u.y = (uint)f2h(v.z) | ((uint)f2h(v.w) << 16);
        *(uint2*)(g_qf + i) = u;
    } else if (bid < 16480) {
        const int bid2 = bid - 16384;
        const int sel = bid2 >> 5;
        const int blk = bid2 & 31;
        const float* src = (sel == 0) ? Wq : (sel == 1) ? Wk : Wv;
        int i = (blk * 256 + tid) * 4;
        float4 v = *(const float4*)(src + i);
        uint2 u;
        u.x = (uint)f2h(v.x) | ((uint)f2h(v.y) << 16);
        u.y = (uint)f2h(v.z) | ((uint)f2h(v.w) << 16);
        *(uint2*)(g_Wf[sel] + i) = u;
    } else {
        int i = (bid - 16480) * 256 + tid;
        out[i] = __int_as_float(0xFF800000);
    }
}

// ---------------- K1: QKV projection (fp16 single-pass, 4 chunks) --------------
__global__ __launch_bounds__(256, 2)
void qkv_mma_kernel(const float* __restrict__ bq, const float* __restrict__ bk,
                    const float* __restrict__ bv) {
    extern __shared__ ushort sh[];
    const int tid = threadIdx.x;
    const int w = tid >> 5, lane = tid & 31, g = lane >> 2, t = lane & 3;
    const int m0 = (w & 3) * 32, n0 = (w >> 2) * 64;
    const int rowBase = blockIdx.x * 128;
    const int sel = blockIdx.y;

    const uint32_t base = smem_u32(sh);
    const uint32_t aoff = a_lane_off(m0, lane), boff = b_lane_off(n0, lane);

    float c[2][8][4];
    #pragma unroll
    for (int i = 0; i < 2; i++)
        #pragma unroll
        for (int j = 0; j < 8; j++)
            #pragma unroll
            for (int r = 0; r < 4; r++) c[i][j][r] = 0.f;

    pipe1_mma<4>(c, base, aoff, boff,
                 g_qf + (size_t)rowBase * Xn, Xn, g_Wf[sel], Xn, tid);

    const float* bias = (sel == 0) ? bq : (sel == 1) ? bk : bv;
    ushort* dst = (sel == 0) ? g_Qf : (sel == 1) ? g_Kf : g_Vf;
    #pragma unroll
    for (int tm = 0; tm < 2; tm++) {
        #pragma unroll
        for (int half = 0; half < 2; half++) {
            const int mloc = m0 + tm * 16 + g + half * 8;
            const size_t row = (size_t)(rowBase + mloc) * Yn;
            #pragma unroll
            for (int tn = 0; tn < 8; tn++) {
                const int n = n0 + tn * 8 + t * 2;
                float v0 = c[tm][tn][half * 2 + 0] + __ldg(bias + n);
                float v1 = c[tm][tn][half * 2 + 1] + __ldg(bias + n + 1);
                *(uint*)(dst + row + n) = (uint)f2h(v0) | ((uint)f2h(v1) << 16);
            }
        }
    }
}

// ---------------- K2: scores (fp16 single-pass) -> P fp16 + sums ---------------
__global__ __launch_bounds__(256, 2)
void scores_mma_kernel() {
    extern __shared__ ushort sh[];
    const int tid = threadIdx.x;
    const int w = tid >> 5, lane = tid & 31, g = lane >> 2, t = lane & 3;
    const int m0 = (w & 3) * 32, n0 = (w >> 2) * 64, mw = w & 3;
    const int kt = blockIdx.x, qt = blockIdx.y, b = blockIdx.z;

    const uint32_t base = smem_u32(sh);
    const uint32_t aoff = a_lane_off(m0, lane), boff = b_lane_off(n0, lane);

    float c[2][8][4];
    #pragma unroll
    for (int i = 0; i < 2; i++)
        #pragma unroll
        for (int j = 0; j < 8; j++)
            #pragma unroll
            for (int r = 0; r < 4; r++) c[i][j][r] = 0.f;

    const size_t qoff = ((size_t)b * Sn + qt * 128) * Yn;
    const size_t koff = ((size_t)b * Sn + kt * 128) * Yn;
    pipe1_mma<2>(c, base, aoff, boff, g_Qf + qoff, Yn, g_Kf + koff, Yn, tid);

    // c := exp(c * scale) in place
    const float scale = 0.08838834764831845f;  // 1/sqrt(128)
    #pragma unroll
    for (int i = 0; i < 2; i++)
        #pragma unroll
        for (int j = 0; j < 8; j++)
            #pragma unroll
            for (int r = 0; r < 4; r++) c[i][j][r] = __expf(c[i][j][r] * scale);

    // write P (fp16)
    ushort* Pp = g_P + (size_t)b * Sn * Sn;
    #pragma unroll
    for (int tm = 0; tm < 2; tm++) {
        #pragma unroll
        for (int half = 0; half < 2; half++) {
            const size_t m = (size_t)(qt * 128 + m0 + tm * 16 + g + half * 8);
            #pragma unroll
            for (int tn = 0; tn < 8; tn++) {
                const int n = kt * 128 + n0 + tn * 8 + t * 2;
                *(uint*)(Pp + m * Sn + n) =
                    (uint)f2h(c[tm][tn][half * 2 + 0]) |
                    ((uint)f2h(c[tm][tn][half * 2 + 1]) << 16);
            }
        }
    }

    // per-tile column sums of exp over this CTA's 128 q rows
    __syncthreads();                       // tiles no longer needed; reuse smem
    float* szz = (float*)sh;               // [128][4]
    float vz[16];
    #pragma unroll
    for (int tn = 0; tn < 8; tn++) {
        #pragma unroll
        for (int par = 0; par < 2; par++) {
            float z = c[0][tn][par] + c[0][tn][2 + par]
                    + c[1][tn][par] + c[1][tn][2 + par];
            z += __shfl_xor_sync(0xFFFFFFFF, z, 4);
            z += __shfl_xor_sync(0xFFFFFFFF, z, 8);
            z += __shfl_xor_sync(0xFFFFFFFF, z, 16);
            vz[tn * 2 + par] = z;
        }
    }
    if (lane < 4) {
        #pragma unroll
        for (int tn = 0; tn < 8; tn++)
            #pragma unroll
            for (int par = 0; par < 2; par++)
                szz[(n0 + tn * 8 + t * 2 + par) * 4 + mw] = vz[tn * 2 + par];
    }
    __syncthreads();
    if (tid < 128) {
        const int n = tid;
        const float z = szz[n * 4 + 0] + szz[n * 4 + 1] + szz[n * 4 + 2] + szz[n * 4 + 3];
        g_pz[((size_t)(b * 8 + qt)) * Sn + kt * 128 + n] = z;
    }
}

// ---------------- K3: V/Z row scale, [k][d] layout ------------------------------
__global__ __launch_bounds__(256)
void vscale_kernel() {
    __shared__ float szr[64];       // 1/Z for k0..k0+63
    const int b  = blockIdx.y;
    const int k0 = blockIdx.x * 64;
    const int tt = threadIdx.x;

    if (tt < 64) {
        const int k = k0 + tt;
        float z = 0.f;
        #pragma unroll
        for (int i = 0; i < 8; i++)
            z += g_pz[((size_t)(b * 8 + i)) * Sn + k];
        szr[tt] = 1.0f / z;
    }
    __syncthreads();

    #pragma unroll
    for (int it = 0; it < 4; it++) {
        const int idx  = it * 256 + tt;
        const int row  = idx >> 4;          // 0..63
        const int col8 = (idx & 15) << 3;   // 0..120
        const float zr = szr[row];
        const size_t off = ((size_t)b * Sn + k0 + row) * Yn + col8;
        uint4 u = *(const uint4*)(g_Vf + off);
        uint4 o;
        o.x = (uint)f2h(h2f((ushort)(u.x      )) * zr) |
              ((uint)f2h(h2f((ushort)(u.x >> 16)) * zr) << 16);
        o.y = (uint)f2h(h2f((ushort)(u.y      )) * zr) |
              ((uint)f2h(h2f((ushort)(u.y >> 16)) * zr) << 16);
        o.z = (uint)f2h(h2f((ushort)(u.z      )) * zr) |
              ((uint)f2h(h2f((ushort)(u.z >> 16)) * zr) << 16);
        o.w = (uint)f2h(h2f((ushort)(u.w      )) * zr) |
              ((uint)f2h(h2f((ushort)(u.w >> 16)) * zr) << 16);
        *(uint4*)(g_Vt + off) = o;
    }
}

// ---------------- K4: PV, 64-q tiles, 4-stage pipeline + fused max -------------
// grid (16, 64). Warp tile 32m x 32n: m0=(w&1)*32, n0=(w>>1)*32.
__global__ __launch_bounds__(256, 2)
void pv_mma_kernel(float* __restrict__ out) {
    extern __shared__ ushort sh[];
    const int tid = threadIdx.x;
    const int w = tid >> 5, lane = tid & 31, t = lane & 3;
    const int m0 = (w & 1) * 32, n0 = (w >> 1) * 32;
    const int qt = blockIdx.x, b = blockIdx.y;

    const uint32_t base = smem_u32(sh);
    const uint32_t aoff = a_lane_off(m0, lane), boff = bT_lane_off(n0, lane);

    const ushort* Pp = g_P + (size_t)b * Sn * Sn + (size_t)(qt * 64) * Sn;
    const ushort* Vp = g_Vt + (size_t)b * Sn * Yn;   // [k][d]

    float c[2][4][4];
    #pragma unroll
    for (int i = 0; i < 2; i++)
        #pragma unroll
        for (int j = 0; j < 4; j++)
            #pragma unroll
            for (int r = 0; r < 4; r++) c[i][j][r] = 0.f;

    // 4-stage pipeline, prefetch distance 3
    #pragma unroll
    for (int s = 0; s < 3; s++) {
        fill_tileA64_async(base + PA(s), Pp + s * 64, Sn, tid);
        fill_tileB_async  (base + PB(s), Vp + (size_t)s * 64 * Yn, tid);
        CP_COMMIT();
    }
    #pragma unroll
    for (int ch = 0; ch < 16; ch++) {
        const int st = ch & 3;
        if (ch < 14)      { CP_WAIT(2); }
        else if (ch == 14){ CP_WAIT(1); }
        else              { CP_WAIT(0); }
        __syncthreads();
        if (ch + 3 < 16) {
            const int sn = (ch + 3) & 3;
            fill_tileA64_async(base + PA(sn), Pp + (ch + 3) * 64, Sn, tid);
            fill_tileB_async  (base + PB(sn), Vp + (size_t)(ch + 3) * 64 * Yn, tid);
            CP_COMMIT();
        }
        warp_mma32_trans(c, base + PA(st) + aoff, base + PB(st) + boff);
    }

    // fused max over q: thread-local max, shuffle-reduce over g, one atomic per n.
    #pragma unroll
    for (int tn = 0; tn < 4; tn++) {
        #pragma unroll
        for (int par = 0; par < 2; par++) {
            float v = c[0][tn][par];
            v = fmaxf(v, c[0][tn][2 + par]);
            v = fmaxf(v, c[1][tn][par]);
            v = fmaxf(v, c[1][tn][2 + par]);
            v = fmaxf(v, __shfl_xor_sync(0xFFFFFFFF, v, 4));
            v = fmaxf(v, __shfl_xor_sync(0xFFFFFFFF, v, 8));
            v = fmaxf(v, __shfl_xor_sync(0xFFFFFFFF, v, 16));
            if (lane < 4)
                atomicMaxF(out + b * Yn + n0 + tn * 8 + t * 2 + par, v);
        }
    }
}

// ============================================================================
extern "C" void kernel_launch(void* const* d_in, const int* in_sizes, int n_in,
                              void* d_out, int out_size)
{
    const float* q  = (const float*)d_in[0];
    const float* Wq = (const float*)d_in[1];
    const float* bq = (const float*)d_in[2];
    const float* Wk = (const float*)d_in[3];
    const float* bk = (const float*)d_in[4];
    const float* Wv = (const float*)d_in[5];
    const float* bv = (const float*)d_in[6];
    float* out = (float*)d_out;

    cudaFuncSetAttribute(qkv_mma_kernel,    cudaFuncAttributeMaxDynamicSharedMemorySize, SM_1P);
    cudaFuncSetAttribute(scores_mma_kernel, cudaFuncAttributeMaxDynamicSharedMemorySize, SM_1P);
    cudaFuncSetAttribute(pv_mma_kernel,     cudaFuncAttributeMaxDynamicSharedMemorySize, SM_PV);

    prep_kernel<<<16512, 256>>>(q, Wq, Wk, Wv, out);
    qkv_mma_kernel<<<dim3(Bn * Sn / 128, 3), 256, SM_1P>>>(bq, bk, bv);
    scores_mma_kernel<<<dim3(Sn / 128, Sn / 128, Bn), 256, SM_1P>>>();
    vscale_kernel<<<dim3(Sn / 64, Bn), 256>>>();
    pv_mma_kernel<<<dim3(Sn / 64, Bn), 256, SM_PV>>>(out);
}